// round 8
// baseline (speedup 1.0000x reference)
#include <cuda_runtime.h>
#include <cstdint>
#include <math.h>

// ---------------------------------------------------------------------------
// Problem constants
//   output  : float32 [64, 1000]       (64000 elems)
//   target  : int64/int32 [64]         (64 elems)
//   feats_a : float32 [3, 64, 65536]   (12582912 elems)
//   feats_b : float32 [4, 64, 32768]   (8388608 elems)
//   out     : float32 [base + 64000]   (loss..., logits passthrough)
// Inputs are bound BY SIZE, not by position.
// ---------------------------------------------------------------------------

#define NS      64          // N samples
#define KT      32          // k-tile width per smem stage
#define CHUNK   512         // D-columns per CTA in gram kernel
#define NIT     (CHUNK/KT)  // 16 stages per CTA
#define STRIDE  36          // smem row stride (words) -> conflict-free frags
#define CA      128         // chunks per feats_a feature (65536/512)
#define CB      64          // chunks per feats_b feature (32768/512)
#define NBLK    (3*CA + 4*CB)   // 640 gram CTAs

__device__ float  g_partial[(size_t)NBLK * 4096];   // per-CTA partial Grams
__device__ double g_K[7 * 4096];                    // reduced Grams, diag zeroed
__device__ double g_rs[7 * 64];                     // row sums
__device__ double g_trkl[16];                       // pair dot products
__device__ double g_rowce[64];                      // per-row log-prob of target

__device__ __forceinline__ unsigned f2tf32(float x) {
    unsigned u;
    asm("cvt.rna.tf32.f32 %0, %1;" : "=r"(u) : "f"(x));
    return u;
}

__device__ __forceinline__ void mma_tf32(float c[4], const unsigned a[4], const unsigned b[2]) {
    asm volatile(
        "mma.sync.aligned.m16n8k8.row.col.f32.tf32.tf32.f32 "
        "{%0,%1,%2,%3}, {%4,%5,%6,%7}, {%8,%9}, {%0,%1,%2,%3};\n"
        : "+f"(c[0]), "+f"(c[1]), "+f"(c[2]), "+f"(c[3])
        : "r"(a[0]), "r"(a[1]), "r"(a[2]), "r"(a[3]), "r"(b[0]), "r"(b[1]));
}

// ---------------------------------------------------------------------------
// Kernel 1: partial Gram matrices via tf32 tensor-core mma.
// Each CTA: one feature, one 512-column D-chunk. 4 warps, each a 32x32 tile
// of the 64x64 output. Double-buffered smem stages of 64x32 fp32 (as tf32).
// ---------------------------------------------------------------------------
__global__ __launch_bounds__(128) void gram_kernel(const float* __restrict__ fa,
                                                   const float* __restrict__ fb) {
    __shared__ unsigned tile[2][64 * STRIDE];

    int bid = blockIdx.x;
    const float* X;
    int D, c0;
    if (bid < 3 * CA) {
        int f = bid / CA, ch = bid % CA;
        D = 65536; X = fa + (size_t)f * NS * D; c0 = ch * CHUNK;
    } else {
        int t = bid - 3 * CA;
        int f = t / CB, ch = t % CB;
        D = 32768; X = fb + (size_t)f * NS * D; c0 = ch * CHUNK;
    }

    const int tid  = threadIdx.x;
    const int lane = tid & 31, wid = tid >> 5;
    const int g = lane >> 2, t4 = lane & 3;
    const int wm = wid >> 1, wn = wid & 1;

    // gmem -> smem staging indices: 512 float4s, 4 per thread
    int r_[4], cv_[4];
#pragma unroll
    for (int j = 0; j < 4; j++) { int idx = tid + j * 128; r_[j] = idx >> 3; cv_[j] = idx & 7; }

    float4 ld[4];
    float  c[2][4][4];
#pragma unroll
    for (int mi = 0; mi < 2; mi++)
#pragma unroll
        for (int ni = 0; ni < 4; ni++)
#pragma unroll
            for (int k = 0; k < 4; k++) c[mi][ni][k] = 0.f;

    auto LOAD = [&](int it) {
        int gcol = c0 + it * KT;
#pragma unroll
        for (int j = 0; j < 4; j++)
            ld[j] = *reinterpret_cast<const float4*>(X + (size_t)r_[j] * D + gcol + cv_[j] * 4);
    };
    auto STORE = [&](unsigned* buf) {
#pragma unroll
        for (int j = 0; j < 4; j++) {
            uint4 v;
            v.x = f2tf32(ld[j].x); v.y = f2tf32(ld[j].y);
            v.z = f2tf32(ld[j].z); v.w = f2tf32(ld[j].w);
            *reinterpret_cast<uint4*>(&buf[r_[j] * STRIDE + cv_[j] * 4]) = v;
        }
    };

    LOAD(0);
    STORE(tile[0]);
    __syncthreads();

    for (int it = 0; it < NIT; ++it) {
        if (it + 1 < NIT) LOAD(it + 1);
        const unsigned* buf = tile[it & 1];
#pragma unroll
        for (int ks = 0; ks < 4; ++ks) {
            const int kc = ks * 8;
            unsigned a[2][4], b[4][2];
#pragma unroll
            for (int mi = 0; mi < 2; mi++) {
                int r0 = wm * 32 + mi * 16 + g;
                a[mi][0] = buf[r0 * STRIDE + kc + t4];
                a[mi][1] = buf[(r0 + 8) * STRIDE + kc + t4];
                a[mi][2] = buf[r0 * STRIDE + kc + t4 + 4];
                a[mi][3] = buf[(r0 + 8) * STRIDE + kc + t4 + 4];
            }
#pragma unroll
            for (int ni = 0; ni < 4; ni++) {
                int rn = wn * 32 + ni * 8 + g;
                b[ni][0] = buf[rn * STRIDE + kc + t4];
                b[ni][1] = buf[rn * STRIDE + kc + t4 + 4];
            }
#pragma unroll
            for (int mi = 0; mi < 2; mi++)
#pragma unroll
                for (int ni = 0; ni < 4; ni++)
                    mma_tf32(c[mi][ni], a[mi], b[ni]);
        }
        __syncthreads();
        if (it + 1 < NIT) STORE(tile[(it + 1) & 1]);
        __syncthreads();
    }

    // epilogue: write partial Gram
    float* part = g_partial + (size_t)bid * 4096;
#pragma unroll
    for (int mi = 0; mi < 2; mi++)
#pragma unroll
        for (int ni = 0; ni < 4; ni++) {
            int R = wm * 32 + mi * 16 + g;
            int C = wn * 32 + ni * 8 + 2 * t4;
            part[R * 64 + C]           = c[mi][ni][0];
            part[R * 64 + C + 1]       = c[mi][ni][1];
            part[(R + 8) * 64 + C]     = c[mi][ni][2];
            part[(R + 8) * 64 + C + 1] = c[mi][ni][3];
        }
}

// ---------------------------------------------------------------------------
// Kernel 2: reduce partial Grams (fp64), zero diagonal.
// Grid: 7 features x 4 sub-blocks; 512 threads; coalesced over entries.
// ---------------------------------------------------------------------------
__global__ __launch_bounds__(512) void reduce_gram() {
    int f = blockIdx.x >> 2, sub = blockIdx.x & 3;
    int base, nch;
    if (f < 3) { base = f * CA;                nch = CA; }
    else       { base = 3 * CA + (f - 3) * CB; nch = CB; }

    int e_end = sub * 1024 + 1024;
    for (int e = sub * 1024 + threadIdx.x; e < e_end; e += 512) {
        double acc = 0.0;
        const float* p = g_partial + (size_t)base * 4096 + e;
        for (int ch = 0; ch < nch; ++ch) acc += (double)p[(size_t)ch * 4096];
        if ((e >> 6) == (e & 63)) acc = 0.0;
        g_K[f * 4096 + e] = acc;
    }
}

// ---------------------------------------------------------------------------
// Kernel 3: per-row log-softmax CE term + logits passthrough copy.
// Grid: 64 CTAs (one per row), 256 threads. Target dtype auto-detected:
// if any of the 64 int64-interpreted values is outside [0,1000), the buffer
// is treated as int32.
// ---------------------------------------------------------------------------
__global__ __launch_bounds__(256) void ce_copy(const float* __restrict__ logits,
                                               const void* __restrict__ tgt_raw,
                                               float* __restrict__ out, int out_size) {
    __shared__ float  sm[256];
    __shared__ double sd[256];
    int row = blockIdx.x, tid = threadIdx.x;
    const float* x = logits + row * 1000;

    float m = -1e30f;
    for (int cc = tid; cc < 1000; cc += 256) m = fmaxf(m, x[cc]);
    sm[tid] = m; __syncthreads();
    for (int s = 128; s > 0; s >>= 1) { if (tid < s) sm[tid] = fmaxf(sm[tid], sm[tid + s]); __syncthreads(); }
    float mv = sm[0];

    double a = 0.0;
    for (int cc = tid; cc < 1000; cc += 256) a += exp((double)(x[cc] - mv));
    sd[tid] = a; __syncthreads();
    for (int s = 128; s > 0; s >>= 1) { if (tid < s) sd[tid] += sd[tid + s]; __syncthreads(); }

    if (tid == 0) {
        const long long* t64 = (const long long*)tgt_raw;
        const int*       t32 = (const int*)tgt_raw;
        bool is64 = true;
        for (int f = 0; f < 64; f++) {
            long long v = t64[f];
            if (v < 0 || v >= 1000) { is64 = false; break; }
        }
        long long tt = is64 ? t64[row] : (long long)t32[row];
        if (tt < 0) tt = 0;
        if (tt > 999) tt = 999;
        g_rowce[row] = (double)x[tt] - (double)mv - log(sd[0]);
    }

    int base = out_size - 64000;
    for (int cc = tid; cc < 1000; cc += 256) {
        int o = base + row * 1000 + cc;
        if (o >= 0 && o < out_size) out[o] = x[cc];
    }
}

// ---------------------------------------------------------------------------
// Kernel 4: pair dot-products tr(Ki Kj) (16 CTAs) + row sums (CTA 16).
// ---------------------------------------------------------------------------
__device__ __constant__ int c_pi[16] = {0,0,0,1,1,2, 3,3,3,3,4,4,4,5,5,6};
__device__ __constant__ int c_pj[16] = {0,1,2,1,2,2, 3,4,5,6,4,5,6,5,6,6};

__global__ __launch_bounds__(256) void pair_kernel() {
    __shared__ double red[256];
    int p = blockIdx.x, tid = threadIdx.x;
    if (p < 16) {
        const double* Ki = g_K + c_pi[p] * 4096;
        const double* Kj = g_K + c_pj[p] * 4096;
        double a = 0.0;
        for (int e = tid; e < 4096; e += 256) a += Ki[e] * Kj[e];
        red[tid] = a; __syncthreads();
        for (int s = 128; s > 0; s >>= 1) { if (tid < s) red[tid] += red[tid + s]; __syncthreads(); }
        if (tid == 0) g_trkl[p] = red[0];
    } else {
        for (int idx = tid; idx < 448; idx += 256) {
            int f = idx >> 6, n = idx & 63;
            const double* Kf = g_K + f * 4096 + n * 64;
            double a = 0.0;
#pragma unroll
            for (int m = 0; m < 64; m++) a += Kf[m];
            g_rs[idx] = a;
        }
    }
}

// ---------------------------------------------------------------------------
// Kernel 5: HSIC -> CKA -> loss. 1 CTA, 64 threads.
// hsic = (tr(KiKj) + s_i s_j/((N-1)(N-2)) - 2 <r_i,r_j>/(N-2)) / (N(N-3))
// ---------------------------------------------------------------------------
__global__ __launch_bounds__(64) void finalize(float* __restrict__ out, int out_size) {
    __shared__ double rr_s[16];
    __shared__ double s_s[7];
    int tid = threadIdx.x;

    if (tid < 16) {
        int i = c_pi[tid], j = c_pj[tid];
        double a = 0.0;
        for (int n = 0; n < 64; n++) a += g_rs[i * 64 + n] * g_rs[j * 64 + n];
        rr_s[tid] = a;
    }
    if (tid >= 32 && tid < 39) {
        int f = tid - 32;
        double a = 0.0;
        for (int n = 0; n < 64; n++) a += g_rs[f * 64 + n];
        s_s[f] = a;
    }
    __syncthreads();

    if (tid == 0) {
        const double N = 64.0;
        double h[7][7];
        for (int p = 0; p < 16; p++) {
            int i = c_pi[p], j = c_pj[p];
            double hv = (g_trkl[p] + s_s[i] * s_s[j] / ((N - 1.0) * (N - 2.0))
                         - 2.0 * rr_s[p] / (N - 2.0)) / (N * (N - 3.0));
            h[i][j] = hv; h[j][i] = hv;
        }
        double d[7];
        for (int f = 0; f < 7; f++) d[f] = sqrt(h[f][f]);
        double cka = 0.0;
        for (int i = 0; i < 3; i++)
            for (int j = 0; j < 3; j++) cka += h[i][j] / (d[i] * d[j]);
        for (int i = 3; i < 7; i++)
            for (int j = 3; j < 7; j++) cka += h[i][j] / (d[i] * d[j]);
        double ce = 0.0;
        for (int n = 0; n < 64; n++) ce += g_rowce[n];
        ce = -ce / 64.0;
        float loss = (float)(ce + 0.1 * cka);
        int base = out_size - 64000;
        if (base < 1) base = (out_size > 0 ? 1 : 0);
        for (int k = 0; k < base && k < out_size; k++) out[k] = loss;
    }
}

// ---------------------------------------------------------------------------
// Host: bind inputs BY ELEMENT COUNT (robust to metadata ordering).
// ---------------------------------------------------------------------------
extern "C" void kernel_launch(void* const* d_in, const int* in_sizes, int n_in,
                              void* d_out, int out_size) {
    const float* output = nullptr;
    const void*  target = nullptr;
    const float* fa     = nullptr;
    const float* fb     = nullptr;

    for (int i = 0; i < n_in; i++) {
        switch (in_sizes[i]) {
            case 64000:     output = (const float*)d_in[i]; break;
            case 64:        target = d_in[i];               break;
            case 12582912:  fa     = (const float*)d_in[i]; break;
            case 8388608:   fb     = (const float*)d_in[i]; break;
            default: break;
        }
    }
    if (!output || !target || !fa || !fb) {
        // Unexpected shapes: do a minimal safe launch so capture has >=1 node,
        // producing a wrong-but-not-crashing result for diagnosis.
        finalize<<<1, 64>>>((float*)d_out, 0);
        return;
    }

    float* out = (float*)d_out;
    gram_kernel<<<NBLK, 128>>>(fa, fb);
    reduce_gram<<<28, 512>>>();
    ce_copy<<<64, 256>>>(output, target, out, out_size);
    pair_kernel<<<17, 256>>>();
    finalize<<<1, 64>>>(out, out_size);
}

// round 10
// speedup vs baseline: 1.8864x; 1.8864x over previous
#include <cuda_runtime.h>
#include <cstdint>
#include <math.h>

// ---------------------------------------------------------------------------
//   output  : float32 [64, 1000]       (64000 elems)
//   target  : int64/int32 [64]         (64 elems)
//   feats_a : float32 [3, 64, 65536]   (12582912 elems)
//   feats_b : float32 [4, 64, 32768]   (8388608 elems)
//   out     : float32 [base + 64000]   (loss..., logits passthrough)
// Inputs bound BY SIZE. 3 launches: gram+ce -> reduce+rowsum -> pair+finalize.
// ---------------------------------------------------------------------------

#define NS      64
#define KT      64              // k-columns per smem stage
#define CHUNK   1024            // D-columns per gram CTA
#define NIT     (CHUNK/KT)      // 16 stages
#define STRIDE  68              // smem row stride in words (4*17: conflict-free, 16B aligned)
#define CA      64              // chunks per feats_a feature (65536/1024)
#define CB      32              // chunks per feats_b feature (32768/1024)
#define NBLK    (3*CA + 4*CB)   // 320 gram CTAs
#define CEB     64              // fused CE blocks

__device__ float  g_partial[(size_t)NBLK * 4096];
__device__ double g_K[7 * 4096];
__device__ double g_rs[7 * 64];
__device__ double g_trkl[16];
__device__ double g_rowce[64];
__device__ int    g_ctr;        // zero-init; self-resetting

__device__ __constant__ int c_pi[16] = {0,0,0,1,1,2, 3,3,3,3,4,4,4,5,5,6};
__device__ __constant__ int c_pj[16] = {0,1,2,1,2,2, 3,4,5,6,4,5,6,5,6,6};

__device__ __forceinline__ unsigned f2tf32(float x) {
    unsigned u;
    asm("cvt.rna.tf32.f32 %0, %1;" : "=r"(u) : "f"(x));
    return u;
}

__device__ __forceinline__ void mma_tf32(float c[4], const unsigned a[4], const unsigned b[2]) {
    asm volatile(
        "mma.sync.aligned.m16n8k8.row.col.f32.tf32.tf32.f32 "
        "{%0,%1,%2,%3}, {%4,%5,%6,%7}, {%8,%9}, {%0,%1,%2,%3};\n"
        : "+f"(c[0]), "+f"(c[1]), "+f"(c[2]), "+f"(c[3])
        : "r"(a[0]), "r"(a[1]), "r"(a[2]), "r"(a[3]), "r"(b[0]), "r"(b[1]));
}

// ---------------------------------------------------------------------------
// Kernel A: blocks [0,320): partial Grams (tf32 mma, single-sync double buffer)
//           blocks [320,384): per-row log-softmax CE + logits passthrough
// ---------------------------------------------------------------------------
__global__ __launch_bounds__(128) void gram_ce(const float* __restrict__ fa,
                                               const float* __restrict__ fb,
                                               const float* __restrict__ logits,
                                               const void*  __restrict__ tgt_raw,
                                               float* __restrict__ out, int out_size) {
    const int bid = blockIdx.x;
    const int tid = threadIdx.x;
    const int lane = tid & 31, wid = tid >> 5;

    if (bid >= NBLK) {
        // ------------------ fused CE + copy ------------------
        __shared__ float  smx[4];
        __shared__ double sdx[4];
        const int row = bid - NBLK;
        const float* x = logits + row * 1000;

        float m = -1e30f;
        for (int cc = tid; cc < 1000; cc += 128) m = fmaxf(m, x[cc]);
#pragma unroll
        for (int o = 16; o; o >>= 1) m = fmaxf(m, __shfl_xor_sync(0xffffffffu, m, o));
        if (lane == 0) smx[wid] = m;
        __syncthreads();
        const float mv = fmaxf(fmaxf(smx[0], smx[1]), fmaxf(smx[2], smx[3]));

        double a = 0.0;
        for (int cc = tid; cc < 1000; cc += 128) a += (double)expf(x[cc] - mv);
#pragma unroll
        for (int o = 16; o; o >>= 1) a += __shfl_xor_sync(0xffffffffu, a, o);
        if (lane == 0) sdx[wid] = a;

        // parallel dtype detect (no serial break!)
        int ok = 1;
        if (tid < 64) {
            long long v = ((const long long*)tgt_raw)[tid];
            ok = (v >= 0 && v < 1000);
        }
        int is64 = __syncthreads_and(ok);

        if (tid == 0) {
            double tot = sdx[0] + sdx[1] + sdx[2] + sdx[3];
            long long tt = is64 ? ((const long long*)tgt_raw)[row]
                                : (long long)((const int*)tgt_raw)[row];
            if (tt < 0) tt = 0;
            if (tt > 999) tt = 999;
            g_rowce[row] = (double)x[tt] - (double)mv - log(tot);
        }

        int base = out_size - 64000;
        for (int cc = tid; cc < 1000; cc += 128) {
            int o = base + row * 1000 + cc;
            if (o >= 0 && o < out_size) out[o] = x[cc];
        }
        return;
    }

    // ------------------ gram CTA ------------------
    __shared__ unsigned tile[2][64 * STRIDE];

    const float* X;
    int D, c0;
    if (bid < 3 * CA) {
        int f = bid / CA, ch = bid % CA;
        D = 65536; X = fa + (size_t)f * NS * D; c0 = ch * CHUNK;
    } else {
        int t = bid - 3 * CA;
        int f = t / CB, ch = t % CB;
        D = 32768; X = fb + (size_t)f * NS * D; c0 = ch * CHUNK;
    }

    const int g = lane >> 2, t4 = lane & 3;
    const int wm = wid >> 1, wn = wid & 1;

    // staging: 64 rows x 64 cols per stage = 1024 float4s, 8 per thread
    int r_[8], cq_[8];
#pragma unroll
    for (int j = 0; j < 8; j++) { int idx = tid + j * 128; r_[j] = idx >> 4; cq_[j] = idx & 15; }

    float4 ld[8];
    float  c[2][4][4];
#pragma unroll
    for (int mi = 0; mi < 2; mi++)
#pragma unroll
        for (int ni = 0; ni < 4; ni++)
#pragma unroll
            for (int k = 0; k < 4; k++) c[mi][ni][k] = 0.f;

    auto LOAD = [&](int it) {
        int gcol = c0 + it * KT;
#pragma unroll
        for (int j = 0; j < 8; j++)
            ld[j] = *reinterpret_cast<const float4*>(X + (size_t)r_[j] * D + gcol + cq_[j] * 4);
    };
    auto STORE = [&](unsigned* buf) {
#pragma unroll
        for (int j = 0; j < 8; j++) {
            uint4 v;
            v.x = f2tf32(ld[j].x); v.y = f2tf32(ld[j].y);
            v.z = f2tf32(ld[j].z); v.w = f2tf32(ld[j].w);
            *reinterpret_cast<uint4*>(&buf[r_[j] * STRIDE + cq_[j] * 4]) = v;
        }
    };

    LOAD(0);
    STORE(tile[0]);
    __syncthreads();

    for (int it = 0; it < NIT; ++it) {
        if (it + 1 < NIT) LOAD(it + 1);
        const unsigned* buf = tile[it & 1];
#pragma unroll
        for (int ks = 0; ks < KT / 8; ++ks) {
            const int kc = ks * 8;
            unsigned a[2][4], b[4][2];
#pragma unroll
            for (int mi = 0; mi < 2; mi++) {
                int r0 = wm * 32 + mi * 16 + g;
                a[mi][0] = buf[r0 * STRIDE + kc + t4];
                a[mi][1] = buf[(r0 + 8) * STRIDE + kc + t4];
                a[mi][2] = buf[r0 * STRIDE + kc + t4 + 4];
                a[mi][3] = buf[(r0 + 8) * STRIDE + kc + t4 + 4];
            }
#pragma unroll
            for (int ni = 0; ni < 4; ni++) {
                int rn = wn * 32 + ni * 8 + g;
                b[ni][0] = buf[rn * STRIDE + kc + t4];
                b[ni][1] = buf[rn * STRIDE + kc + t4 + 4];
            }
#pragma unroll
            for (int mi = 0; mi < 2; mi++)
#pragma unroll
                for (int ni = 0; ni < 4; ni++)
                    mma_tf32(c[mi][ni], a[mi], b[ni]);
        }
        // single barrier: tile[(it+1)&1]'s last readers were in iteration it-1,
        // already fenced by the barrier that ended it-1.
        if (it + 1 < NIT) STORE(tile[(it + 1) & 1]);
        __syncthreads();
    }

    float* part = g_partial + (size_t)bid * 4096;
#pragma unroll
    for (int mi = 0; mi < 2; mi++)
#pragma unroll
        for (int ni = 0; ni < 4; ni++) {
            int R = wm * 32 + mi * 16 + g;
            int C = wn * 32 + ni * 8 + 2 * t4;
            part[R * 64 + C]           = c[mi][ni][0];
            part[R * 64 + C + 1]       = c[mi][ni][1];
            part[(R + 8) * 64 + C]     = c[mi][ni][2];
            part[(R + 8) * 64 + C + 1] = c[mi][ni][3];
        }
}

// ---------------------------------------------------------------------------
// Kernel B: reduce partials (fp64, 4-way MLP), zero diag, fused row sums.
// Grid: 7 features x 8 sub-blocks (8 rows each); 512 threads (1 entry each).
// ---------------------------------------------------------------------------
__global__ __launch_bounds__(512) void reduce_gram() {
    const int f = blockIdx.x >> 3, sub = blockIdx.x & 7;
    int base, nch;
    if (f < 3) { base = f * CA;                nch = CA; }
    else       { base = 3 * CA + (f - 3) * CB; nch = CB; }

    const int tid = threadIdx.x;
    const int e = sub * 512 + tid;
    const float* p = g_partial + (size_t)base * 4096 + e;

    double a0 = 0.0, a1 = 0.0, a2 = 0.0, a3 = 0.0;
    for (int ch = 0; ch < nch; ch += 4) {
        a0 += (double)p[(size_t)(ch + 0) * 4096];
        a1 += (double)p[(size_t)(ch + 1) * 4096];
        a2 += (double)p[(size_t)(ch + 2) * 4096];
        a3 += (double)p[(size_t)(ch + 3) * 4096];
    }
    double acc = (a0 + a1) + (a2 + a3);
    if ((e >> 6) == (e & 63)) acc = 0.0;
    g_K[f * 4096 + e] = acc;

    // fused row sums: warps (2j, 2j+1) cover row sub*8+j
    double r = acc;
#pragma unroll
    for (int o = 16; o; o >>= 1) r += __shfl_xor_sync(0xffffffffu, r, o);
    __shared__ double ws[16];
    const int wid = tid >> 5, lane = tid & 31;
    if (lane == 0) ws[wid] = r;
    __syncthreads();
    if (tid < 8) g_rs[f * 64 + sub * 8 + tid] = ws[2 * tid] + ws[2 * tid + 1];
}

// ---------------------------------------------------------------------------
// Kernel C: 16 CTAs compute tr(Ki Kj); last CTA finalizes HSIC->CKA->loss.
// ---------------------------------------------------------------------------
__global__ __launch_bounds__(512) void pair_finalize(float* __restrict__ out, int out_size) {
    const int p = blockIdx.x, tid = threadIdx.x;
    const int wid = tid >> 5, lane = tid & 31;
    const double* Ki = g_K + c_pi[p] * 4096;
    const double* Kj = g_K + c_pj[p] * 4096;

    double a = 0.0, b = 0.0;
    for (int e = tid; e < 2048; e += 512) {
        a += Ki[e] * Kj[e];
        b += Ki[e + 2048] * Kj[e + 2048];
    }
    double s = a + b;
#pragma unroll
    for (int o = 16; o; o >>= 1) s += __shfl_xor_sync(0xffffffffu, s, o);
    __shared__ double ws[16];
    if (lane == 0) ws[wid] = s;
    __syncthreads();
    if (wid == 0) {
        double v = (lane < 16) ? ws[lane] : 0.0;
#pragma unroll
        for (int o = 16; o; o >>= 1) v += __shfl_xor_sync(0xffffffffu, v, o);
        if (lane == 0) g_trkl[p] = v;
    }

    __threadfence();
    __shared__ int last;
    if (tid == 0) last = (atomicAdd(&g_ctr, 1) == 15);
    __syncthreads();
    if (!last) return;

    // -------- finalize (runs in whichever CTA arrived last) --------
    __shared__ double rr_s[16], s_s[7], ce_w[2];
    if (tid < 16) {
        int i = c_pi[tid], j = c_pj[tid];
        double acc = 0.0;
        for (int n = 0; n < 64; n++) acc += g_rs[i * 64 + n] * g_rs[j * 64 + n];
        rr_s[tid] = acc;
    }
    if (tid >= 32 && tid < 39) {
        int f = tid - 32;
        double acc = 0.0;
        for (int n = 0; n < 64; n++) acc += g_rs[f * 64 + n];
        s_s[f] = acc;
    }
    if (tid >= 64 && tid < 128) {
        double cv = g_rowce[tid - 64];
#pragma unroll
        for (int o = 16; o; o >>= 1) cv += __shfl_xor_sync(0xffffffffu, cv, o);
        if (lane == 0) ce_w[wid - 2] = cv;
    }
    __syncthreads();

    if (tid == 0) {
        const double N = 64.0;
        double h[7][7];
        for (int q = 0; q < 16; q++) {
            int i = c_pi[q], j = c_pj[q];
            double hv = (g_trkl[q] + s_s[i] * s_s[j] / ((N - 1.0) * (N - 2.0))
                         - 2.0 * rr_s[q] / (N - 2.0)) / (N * (N - 3.0));
            h[i][j] = hv; h[j][i] = hv;
        }
        double d[7];
        for (int f = 0; f < 7; f++) d[f] = sqrt(h[f][f]);
        double cka = 0.0;
        for (int i = 0; i < 3; i++)
            for (int j = 0; j < 3; j++) cka += h[i][j] / (d[i] * d[j]);
        for (int i = 3; i < 7; i++)
            for (int j = 3; j < 7; j++) cka += h[i][j] / (d[i] * d[j]);
        double ce = -(ce_w[0] + ce_w[1]) / 64.0;
        float loss = (float)(ce + 0.1 * cka);
        int base = out_size - 64000;
        if (base < 1) base = (out_size > 0 ? 1 : 0);
        for (int k = 0; k < base && k < out_size; k++) out[k] = loss;
        g_ctr = 0;   // reset for next graph replay
    }
}

// ---------------------------------------------------------------------------
extern "C" void kernel_launch(void* const* d_in, const int* in_sizes, int n_in,
                              void* d_out, int out_size) {
    const float* output = nullptr;
    const void*  target = nullptr;
    const float* fa     = nullptr;
    const float* fb     = nullptr;

    for (int i = 0; i < n_in; i++) {
        switch (in_sizes[i]) {
            case 64000:     output = (const float*)d_in[i]; break;
            case 64:        target = d_in[i];               break;
            case 12582912:  fa     = (const float*)d_in[i]; break;
            case 8388608:   fb     = (const float*)d_in[i]; break;
            default: break;
        }
    }
    float* out = (float*)d_out;
    if (!output || !target || !fa || !fb) {
        pair_finalize<<<16, 512>>>(out, 0);
        return;
    }

    gram_ce<<<NBLK + CEB, 128>>>(fa, fb, output, target, out, out_size);
    reduce_gram<<<56, 512>>>();
    pair_finalize<<<16, 512>>>(out, out_size);
}